// round 15
// baseline (speedup 1.0000x reference)
#include <cuda_runtime.h>
#include <cuda_bf16.h>
#include <math_constants.h>

// SupPixPool: out[b][c][k] = max over p with spx[b][p]==k of img[b][c][p]
// B=4, C=64, H=W=512 (HW=262144), K=1024. out viewed as [256 channels][1024].
//
// R14: conflict-free sub-slots (RSUB=32, 128KB: slot = k*32+lane -> bank ==
// lane, 1 wavefront per ATOMS) — halves the dominant L1-datapath term that
// the R11 model identified (R11: 2-wavefront ATOMS, datapath-math matched
// measured cycles within 4%). Grid = 148 (1 CTA/SM, perfectly balanced
// contiguous tile chunks, zero idle slots). Depth-1 software prefetch gives
// the MLP that R10's 32 warps lacked (reg budget 64 now, not 32).
// Fully fused single kernel: first-tile-owner CTA initializes a channel's
// accumulator (+flag, spin-safe because all 148 CTAs are co-resident in one
// wave); contributors merge via global atomicMax; ticket-elected last
// contributor decodes in place and self-resets the flags for graph replay.
// Bias +128.0f: values positive -> float order == s32 bit order -> one
// atomicMax(int) combine.

#define HW    262144
#define KSEG  1024
#define BC_TOT 256               // B*C channels
#define NCTA  148                // one CTA per SM, single wave
#define TPCH  8                  // tiles per channel
#define NTILE (BC_TOT * TPCH)    // 2048 tiles
#define TILE  (HW / TPCH)        // 32768 pixels
#define NTHR  1024
#define RSUB  32
#define BIAS  128.0f
#define NEG_INF_BITS 0xFF800000u
#define SLOT_BYTES (KSEG * RSUB * 4)   // 128 KB dynamic smem

__device__ int g_flags[BC_TOT];    // channel accumulator initialized? (self-resetting)
__device__ int g_tickets[BC_TOT];  // merge completion count (self-resetting)

// CTA owning tile t: largest i with floor(i*NTILE/NCTA) <= t.
__device__ __forceinline__ int tile_owner(int t) {
    return (int)((((long)t + 1) * NCTA - 1) / NTILE);
}

__global__ void __launch_bounds__(NTHR, 1) sp_kernel(const float* __restrict__ img,
                                                     const int*   __restrict__ spx,
                                                     int*         __restrict__ out) {
    extern __shared__ int slots[];          // [KSEG * RSUB] = 128 KB
    __shared__ int sh_flag;

    const int tid  = threadIdx.x;
    const int lane = tid & 31;
    const int wid  = tid >> 5;

    const int t0 = (int)(((long)blockIdx.x * NTILE) / NCTA);
    const int t1 = (int)(((long)(blockIdx.x + 1) * NTILE) / NCTA);

    // ---- init slots to -inf ----
    {
        const uint4 v = make_uint4(NEG_INF_BITS, NEG_INF_BITS, NEG_INF_BITS, NEG_INF_BITS);
        uint4* s4p = reinterpret_cast<uint4*>(slots);
        #pragma unroll
        for (int i = tid; i < KSEG * RSUB / 4; i += NTHR)
            s4p[i] = v;
    }

    // ---- init global accumulator for channels whose FIRST tile we own ----
    {
        const int bc0 = (t0 + TPCH - 1) >> 3;   // first channel starting in [t0, t1)
        const int bc1 = (t1 + TPCH - 1) >> 3;
        for (int bc = bc0; bc < bc1; ++bc)
            out[bc * KSEG + tid] = (int)NEG_INF_BITS;
        __threadfence();
        __syncthreads();                        // all init writes fenced
        if (tid == 0)
            for (int bc = bc0; bc < bc1; ++bc)
                atomicExch(&g_flags[bc], 1);
    }
    __syncthreads();

    int* laneslot = slots + lane;               // + k*32 -> bank == lane (conflict-free)

    int t = t0;
    while (t < t1) {
        const int bc   = t >> 3;                    // channel of this span
        const int tend = min(t1, (bc + 1) << 3);    // span = tiles of bc in [t, t1)
        const int*   spxb = spx + (bc >> 6) * HW;
        const float* imgb = img + (size_t)bc * HW;

        const int p0 = (t - (bc << 3)) * TILE;
        const int p1 = (tend - (bc << 3)) * TILE;   // (p1-p0) multiple of 4096*?; uniform iters

        // ---- scatter: depth-1 prefetch; 4096 px per block-iter ----
        {
            int idx = p0 + (tid << 2);
            int4   s = __ldg(reinterpret_cast<const int4*>(spxb + idx));
            float4 v = __ldcs(reinterpret_cast<const float4*>(imgb + idx));
            #pragma unroll 2
            for (; idx + NTHR * 4 < p1; idx += NTHR * 4) {
                const int4   sn = __ldg(reinterpret_cast<const int4*>(spxb + idx + NTHR * 4));
                const float4 vn = __ldcs(reinterpret_cast<const float4*>(imgb + idx + NTHR * 4));
                atomicMax(laneslot + s.x * RSUB, __float_as_int(v.x + BIAS));
                atomicMax(laneslot + s.y * RSUB, __float_as_int(v.y + BIAS));
                atomicMax(laneslot + s.z * RSUB, __float_as_int(v.z + BIAS));
                atomicMax(laneslot + s.w * RSUB, __float_as_int(v.w + BIAS));
                s = sn; v = vn;
            }
            atomicMax(laneslot + s.x * RSUB, __float_as_int(v.x + BIAS));
            atomicMax(laneslot + s.y * RSUB, __float_as_int(v.y + BIAS));
            atomicMax(laneslot + s.z * RSUB, __float_as_int(v.z + BIAS));
            atomicMax(laneslot + s.w * RSUB, __float_as_int(v.w + BIAS));
        }
        __syncthreads();                        // scatters done before merge

        // ---- wait for channel accumulator init (cheap: usually already 1) ----
        if (tid == 0)
            while (atomicAdd(&g_flags[bc], 0) == 0) { }
        __syncthreads();

        // ---- merge: warp w owns segments [w*32, w*32+32); conflict-free LDS
        //      + REDUX max; lane keeps segment wbase+lane -> coalesced atomics.
        int* outg = out + bc * KSEG;
        {
            const int wbase = wid * 32;
            int keep = (int)NEG_INF_BITS;
            #pragma unroll
            for (int i = 0; i < 32; ++i) {
                const int v = slots[(wbase + i) * RSUB + lane];
                const int m = __reduce_max_sync(0xFFFFFFFFu, v);
                if (lane == i) keep = m;
            }
            atomicMax(&outg[wbase + lane], keep);
        }

        // ---- ticket: last contributor decodes channel in place ----
        __threadfence();
        if (tid == 0) {
            const int nctb = tile_owner(bc * TPCH + TPCH - 1) - tile_owner(bc * TPCH);
            sh_flag = (atomicAdd(&g_tickets[bc], 1) == nctb);
        }
        __syncthreads();
        if (sh_flag) {
            const int w = __ldcg(&outg[tid]);
            reinterpret_cast<float*>(outg)[tid] = __int_as_float(w) - BIAS;
            if (tid == 0) { g_tickets[bc] = 0; g_flags[bc] = 0; }   // reset for next replay
        }

        // ---- reset slots if another span follows ----
        if (tend < t1) {
            __syncthreads();                    // merge reads done
            const uint4 v = make_uint4(NEG_INF_BITS, NEG_INF_BITS, NEG_INF_BITS, NEG_INF_BITS);
            uint4* s4p = reinterpret_cast<uint4*>(slots);
            #pragma unroll
            for (int i = tid; i < KSEG * RSUB / 4; i += NTHR)
                s4p[i] = v;
        }
        __syncthreads();

        t = tend;
    }
}

extern "C" void kernel_launch(void* const* d_in, const int* in_sizes, int n_in,
                              void* d_out, int out_size) {
    const float* img = (const float*)d_in[0];   // [4, 64, 512, 512] f32
    const int*   spx = (const int*)d_in[1];     // [4, 512, 512] i32

    static int smem_set = 0;
    if (!smem_set) {
        cudaFuncSetAttribute(sp_kernel,
                             cudaFuncAttributeMaxDynamicSharedMemorySize, SLOT_BYTES);
        smem_set = 1;
    }

    sp_kernel<<<NCTA, NTHR, SLOT_BYTES>>>(img, spx, (int*)d_out);
}